// round 5
// baseline (speedup 1.0000x reference)
#include <cuda_runtime.h>
#include <cuda_bf16.h>
#include <math.h>
#include <stdint.h>

// InnerCos: mean over rows of clamp(1 - cos_sim(x_i, centers[label_i]))
// x: [N, 256] f32, label: [N] i32, centers: [C, 256] f32 -> scalar f32

#define D_DIM 256
#define THREADS 256                // 8 warps
#define NW 8
#define STAGE_ROWS 32              // rows per pipeline stage
#define STAGE_FLOATS (STAGE_ROWS * D_DIM)
#define STAGE_BYTES (STAGE_FLOATS * 4)     // 32 KB
#define NSTAGES 4                  // 128 KB dynamic smem

// Pre-normalized centers (c / ||c||), C <= 256
__device__ float g_cnorm[256 * D_DIM];

// ---------- tiny PTX wrappers ----------
__device__ __forceinline__ uint32_t smem_u32(const void* p) {
    return (uint32_t)__cvta_generic_to_shared(p);
}
#define MBAR_INIT(addr, cnt) \
    asm volatile("mbarrier.init.shared.b64 [%0], %1;" :: "r"(addr), "r"(cnt) : "memory")
#define MBAR_EXPECT_TX(addr, tx) \
    asm volatile("mbarrier.arrive.expect_tx.shared.b64 _, [%0], %1;" :: "r"(addr), "r"(tx) : "memory")
#define MBAR_WAIT(addr, parity) do {                                          \
    uint32_t _m = (addr); uint32_t _p = (parity); uint32_t _done;             \
    asm volatile("{\n\t.reg .pred p;\n\t"                                     \
        "mbarrier.try_wait.parity.acquire.cta.shared::cta.b64 p, [%1], %2;\n\t" \
        "selp.b32 %0, 1, 0, p;\n\t}"                                          \
        : "=r"(_done) : "r"(_m), "r"(_p) : "memory");                         \
    if (!_done) {                                                             \
        asm volatile("{\n\t.reg .pred P1;\n\t"                                \
            "WL_%=:\n\t"                                                      \
            "mbarrier.try_wait.parity.acquire.cta.shared::cta.b64 P1, [%0], %1, 0x989680;\n\t" \
            "@P1 bra.uni WD_%=;\n\t"                                          \
            "bra.uni WL_%=;\n\t"                                              \
            "WD_%=:\n\t}" :: "r"(_m), "r"(_p) : "memory");                    \
    } } while (0)
#define CP_BULK_G2S(dst, src, bytes, mbar) \
    asm volatile("cp.async.bulk.shared::cta.global.mbarrier::complete_tx::bytes [%0], [%1], %2, [%3];" \
        :: "r"(dst), "l"(src), "r"(bytes), "r"(mbar) : "memory")

// ---- Prologue: one warp per center, normalize into g_cnorm ----
__global__ void center_norm_kernel(const float* __restrict__ cen, int C)
{
    const int c    = blockIdx.x;
    const int lane = threadIdx.x;
    const float4* row = reinterpret_cast<const float4*>(cen + (size_t)c * D_DIM);
    float4 v0 = __ldg(row + lane);
    float4 v1 = __ldg(row + lane + 32);
    float s = v0.x*v0.x + v0.y*v0.y + v0.z*v0.z + v0.w*v0.w
            + v1.x*v1.x + v1.y*v1.y + v1.z*v1.z + v1.w*v1.w;
    #pragma unroll
    for (int o = 16; o > 0; o >>= 1)
        s += __shfl_xor_sync(0xffffffffu, s, o);
    float inv = rsqrtf(fmaxf(s, 1e-30f));
    v0.x *= inv; v0.y *= inv; v0.z *= inv; v0.w *= inv;
    v1.x *= inv; v1.y *= inv; v1.z *= inv; v1.w *= inv;
    float4* dst = reinterpret_cast<float4*>(g_cnorm + (size_t)c * D_DIM);
    dst[lane] = v0;
    dst[lane + 32] = v1;
}

// ---- Main: persistent CTAs, 4-deep cp.async.bulk pipeline into smem ----
__global__ void __launch_bounds__(THREADS, 1)
inner_cos_kernel(const float* __restrict__ x,
                 const int* __restrict__ lab,
                 float* __restrict__ out,
                 int N, int stages_total, int per_cta, float invN)
{
    extern __shared__ float sbuf[];                 // NSTAGES * STAGE_FLOATS
    __shared__ __align__(8) unsigned long long full_bar[NSTAGES];
    __shared__ float wsum[NW];

    const int tid  = threadIdx.x;
    const int lane = tid & 31;
    const int warp = tid >> 5;
    const int sub  = lane >> 3;                     // warp's row 0..3
    const int sl   = lane & 7;                      // 8 float4 per lane
    const int row_local = warp * 4 + sub;           // 0..31 within a stage

    const uint32_t sbuf_u  = smem_u32(sbuf);
    const uint32_t bar_u   = smem_u32(full_bar);

    const int s0 = blockIdx.x * per_cta;
    const int s1 = min(s0 + per_cta, stages_total);
    const int nstg = s1 - s0;

    if (tid == 0) {
        #pragma unroll
        for (int k = 0; k < NSTAGES; ++k)
            MBAR_INIT(bar_u + k * 8, 1);
    }
    __syncthreads();

    // ---- prologue: fill the pipeline ----
    if (tid == 0) {
        const int npro = min(NSTAGES, nstg);
        for (int k = 0; k < npro; ++k) {
            const int st = s0 + k;
            MBAR_EXPECT_TX(bar_u + k * 8, (uint32_t)STAGE_BYTES);
            CP_BULK_G2S(sbuf_u + k * STAGE_BYTES,
                        x + (size_t)st * STAGE_FLOATS,
                        (uint32_t)STAGE_BYTES,
                        bar_u + k * 8);
        }
    }

    float acc = 0.0f;

    // prefetch first label
    int lb = 0;
    if (nstg > 0) {
        int r = s0 * STAGE_ROWS + row_local;
        if (r < N) lb = __ldg(lab + r);
    }

    for (int i = s0; i < s1; ++i) {
        const int k     = i - s0;
        const int slot  = k & (NSTAGES - 1);
        const int phase = (k >> 2) & 1;

        MBAR_WAIT(bar_u + slot * 8, (uint32_t)phase);

        const int lb_cur = lb;
        // prefetch next stage's label early
        if (i + 1 < s1) {
            int rn = (i + 1) * STAGE_ROWS + row_local;
            if (rn < N) lb = __ldg(lab + rn);
        }

        const int r = i * STAGE_ROWS + row_local;
        if (r < N) {
            const float4* xr = reinterpret_cast<const float4*>(
                sbuf + (size_t)slot * STAGE_FLOATS + (size_t)row_local * D_DIM);
            const float4* cr = reinterpret_cast<const float4*>(
                g_cnorm + (size_t)lb_cur * D_DIM);

            float4 a[8];
            #pragma unroll
            for (int j = 0; j < 8; ++j)
                a[j] = xr[sl + 8 * j];              // conflict-free LDS.128

            float dot = 0.0f, nx2 = 0.0f;
            #pragma unroll
            for (int j = 0; j < 8; ++j) {
                float4 c = cr[sl + 8 * j];          // L1-resident LDG.128
                dot = fmaf(a[j].x, c.x, fmaf(a[j].y, c.y,
                      fmaf(a[j].z, c.z, fmaf(a[j].w, c.w, dot))));
                nx2 = fmaf(a[j].x, a[j].x, fmaf(a[j].y, a[j].y,
                      fmaf(a[j].z, a[j].z, fmaf(a[j].w, a[j].w, nx2))));
            }

            #pragma unroll
            for (int o = 4; o > 0; o >>= 1) {       // reduce across 8-lane group
                dot += __shfl_xor_sync(0xffffffffu, dot, o);
                nx2 += __shfl_xor_sync(0xffffffffu, nx2, o);
            }

            if (sl == 0) {
                float cos = dot * rsqrtf(fmaxf(nx2, 1e-30f));
                acc += fminf(fmaxf(1.0f - cos, 1e-12f), 1e12f);
            }
        }

        __syncthreads();                            // slot is now free

        if (tid == 0 && i + NSTAGES < s1) {
            const int st = i + NSTAGES;
            MBAR_EXPECT_TX(bar_u + slot * 8, (uint32_t)STAGE_BYTES);
            CP_BULK_G2S(sbuf_u + slot * STAGE_BYTES,
                        x + (size_t)st * STAGE_FLOATS,
                        (uint32_t)STAGE_BYTES,
                        bar_u + slot * 8);
        }
    }

    // ---- final reduction: warp, block, one atomic per CTA ----
    #pragma unroll
    for (int o = 16; o > 0; o >>= 1)
        acc += __shfl_xor_sync(0xffffffffu, acc, o);
    if (lane == 0) wsum[warp] = acc;
    __syncthreads();
    if (tid == 0) {
        float s = 0.0f;
        #pragma unroll
        for (int i = 0; i < NW; ++i) s += wsum[i];
        atomicAdd(out, s * invN);
    }
}

extern "C" void kernel_launch(void* const* d_in, const int* in_sizes, int n_in,
                              void* d_out, int out_size)
{
    const float* x   = (const float*)d_in[0];   // ref_emb [N, 256]
    const int*   lab = (const int*)d_in[1];     // ref_label [N]
    const float* cen = (const float*)d_in[2];   // centers [C, 256]
    float* out = (float*)d_out;

    const int N = in_sizes[1];
    const int C = in_sizes[2] / D_DIM;
    const size_t smem = (size_t)NSTAGES * STAGE_BYTES;   // 128 KB

    static int sm_count = 0;
    if (sm_count == 0) {
        cudaDeviceGetAttribute(&sm_count, cudaDevAttrMultiProcessorCount, 0);
        cudaFuncSetAttribute(inner_cos_kernel,
                             cudaFuncAttributeMaxDynamicSharedMemorySize,
                             (int)smem);
    }

    const int stages_total = (N + STAGE_ROWS - 1) / STAGE_ROWS;
    const int grid = sm_count;                           // persistent, 1 CTA/SM
    const int per_cta = (stages_total + grid - 1) / grid;

    cudaMemsetAsync(d_out, 0, sizeof(float), 0);

    center_norm_kernel<<<C, 32>>>(cen, C);

    inner_cos_kernel<<<grid, THREADS, smem>>>(x, lab, out, N,
                                              stages_total, per_cta,
                                              1.0f / (float)N);
}

// round 6
// speedup vs baseline: 1.0693x; 1.0693x over previous
#include <cuda_runtime.h>
#include <cuda_bf16.h>
#include <math.h>

// InnerCos: mean over rows of clamp(1 - cos_sim(x_i, centers[label_i]))
// x: [N, 256] f32, label: [N] i32, centers: [C, 256] f32 -> scalar f32

#define D_DIM 256
#define THREADS 256               // 8 warps
#define NW (THREADS / 32)
#define ROWS_PER_BLOCK 256
#define GROUPS 8                  // iterations; 32 rows consumed per iter

// Pre-normalized centers (c / ||c||), C <= 256
__device__ float g_cnorm[256 * D_DIM];

// ---- Prologue: one warp per center, normalize into g_cnorm; also zero out ----
__global__ void center_norm_kernel(const float* __restrict__ cen, int C,
                                   float* __restrict__ out)
{
    const int c    = blockIdx.x;
    const int lane = threadIdx.x;
    if (c == 0 && lane == 0) *out = 0.0f;
    const float4* row = reinterpret_cast<const float4*>(cen + (size_t)c * D_DIM);
    float4 v0 = __ldg(row + lane);
    float4 v1 = __ldg(row + lane + 32);
    float s = v0.x*v0.x + v0.y*v0.y + v0.z*v0.z + v0.w*v0.w
            + v1.x*v1.x + v1.y*v1.y + v1.z*v1.z + v1.w*v1.w;
    #pragma unroll
    for (int o = 16; o > 0; o >>= 1)
        s += __shfl_xor_sync(0xffffffffu, s, o);
    float inv = rsqrtf(fmaxf(s, 1e-30f));
    v0.x *= inv; v0.y *= inv; v0.z *= inv; v0.w *= inv;
    v1.x *= inv; v1.y *= inv; v1.z *= inv; v1.w *= inv;
    float4* dst = reinterpret_cast<float4*>(g_cnorm + (size_t)c * D_DIM);
    dst[lane] = v0;
    dst[lane + 32] = v1;
}

// ---- Main: 8 lanes/row, 4 rows/warp, register double-buffered x loads ----
__global__ void __launch_bounds__(THREADS, 3)
inner_cos_kernel(const float* __restrict__ x,
                 const int* __restrict__ lab,
                 float* __restrict__ out,
                 int N, float invN)
{
    const int tid  = threadIdx.x;
    const int lane = tid & 31;
    const int warp = tid >> 5;
    const int sub  = lane >> 3;   // warp's row 0..3 within a group
    const int sl   = lane & 7;    // owns 8 float4 of the row

    // row for iteration it: rbase + it * 32
    const int rbase = blockIdx.x * ROWS_PER_BLOCK + warp * 4 + sub;

    float acc = 0.0f;

    // ---- prologue of the register pipeline: group 0 loads ----
    int   r0  = rbase;
    int   lb  = (r0 < N) ? __ldg(lab + r0) : 0;
    float4 a[8];
    {
        const float4* xr = reinterpret_cast<const float4*>(
            x + (size_t)min(r0, N - 1) * D_DIM);
        #pragma unroll
        for (int j = 0; j < 8; ++j)
            a[j] = __ldg(xr + sl + 8 * j);
    }

    #pragma unroll
    for (int it = 0; it < GROUPS; ++it) {
        const bool v      = (rbase + it * 32) < N;
        const int  lb_cur = lb;

        // ---- issue NEXT group's loads first (keep DRAM queue full) ----
        float4 b[8];
        if (it + 1 < GROUPS) {
            const int rn = rbase + (it + 1) * 32;
            lb = (rn < N) ? __ldg(lab + rn) : 0;
            const float4* xn = reinterpret_cast<const float4*>(
                x + (size_t)min(rn, N - 1) * D_DIM);
            #pragma unroll
            for (int j = 0; j < 8; ++j)
                b[j] = __ldg(xn + sl + 8 * j);
        }

        // ---- compute on CURRENT group (a[], lb_cur) ----
        const float4* cr = reinterpret_cast<const float4*>(
            g_cnorm + (size_t)lb_cur * D_DIM);

        float dot0 = 0.f, dot1 = 0.f, nx0 = 0.f, nx1 = 0.f;
        #pragma unroll
        for (int j = 0; j < 8; j += 2) {
            float4 c0 = cr[sl + 8 * j];        // L1-resident
            float4 c1 = cr[sl + 8 * (j + 1)];
            dot0 = fmaf(a[j].x, c0.x, fmaf(a[j].y, c0.y,
                   fmaf(a[j].z, c0.z, fmaf(a[j].w, c0.w, dot0))));
            nx0  = fmaf(a[j].x, a[j].x, fmaf(a[j].y, a[j].y,
                   fmaf(a[j].z, a[j].z, fmaf(a[j].w, a[j].w, nx0))));
            dot1 = fmaf(a[j+1].x, c1.x, fmaf(a[j+1].y, c1.y,
                   fmaf(a[j+1].z, c1.z, fmaf(a[j+1].w, c1.w, dot1))));
            nx1  = fmaf(a[j+1].x, a[j+1].x, fmaf(a[j+1].y, a[j+1].y,
                   fmaf(a[j+1].z, a[j+1].z, fmaf(a[j+1].w, a[j+1].w, nx1))));
        }
        float dot = dot0 + dot1;
        float nx2 = nx0 + nx1;

        #pragma unroll
        for (int o = 4; o > 0; o >>= 1) {      // reduce across the 8-lane group
            dot += __shfl_xor_sync(0xffffffffu, dot, o);
            nx2 += __shfl_xor_sync(0xffffffffu, nx2, o);
        }

        if (sl == 0 && v) {
            float cos = dot * rsqrtf(fmaxf(nx2, 1e-30f));
            acc += fminf(fmaxf(1.0f - cos, 1e-12f), 1e12f);
        }

        // ---- rotate pipeline ----
        if (it + 1 < GROUPS) {
            #pragma unroll
            for (int j = 0; j < 8; ++j) a[j] = b[j];
        }
    }

    // ---- warp reduce (acc nonzero only on sl==0 lanes), block, one atomic ----
    #pragma unroll
    for (int o = 16; o > 0; o >>= 1)
        acc += __shfl_xor_sync(0xffffffffu, acc, o);

    __shared__ float wsum[NW];
    if (lane == 0) wsum[warp] = acc;
    __syncthreads();
    if (tid == 0) {
        float s = 0.0f;
        #pragma unroll
        for (int i = 0; i < NW; ++i) s += wsum[i];
        atomicAdd(out, s * invN);
    }
}

extern "C" void kernel_launch(void* const* d_in, const int* in_sizes, int n_in,
                              void* d_out, int out_size)
{
    const float* x   = (const float*)d_in[0];   // ref_emb [N, 256]
    const int*   lab = (const int*)d_in[1];     // ref_label [N]
    const float* cen = (const float*)d_in[2];   // centers [C, 256]
    float* out = (float*)d_out;

    const int N = in_sizes[1];
    const int C = in_sizes[2] / D_DIM;

    center_norm_kernel<<<C, 32>>>(cen, C, out);

    const int blocks = (N + ROWS_PER_BLOCK - 1) / ROWS_PER_BLOCK;
    inner_cos_kernel<<<blocks, THREADS>>>(x, lab, out, N, 1.0f / (float)N);
}